// round 9
// baseline (speedup 1.0000x reference)
#include <cuda_runtime.h>
#include <cuda_bf16.h>
#include <math.h>
#include <cstdint>

#define BATCH 4096
#define T 64
#define HID 256
#define INDIM 192
#define NCTA 128

// ---------------- device scratch ----------------
__device__ float g_proj[3][(size_t)T * BATCH * HID];              // input projections
__device__ __nv_bfloat16 g_wbf[3][2][HID * HID];                  // W_rec hi/lo bf16
__device__ __nv_bfloat16 g_wbf_in[3][2][HID * INDIM];             // W_in hi/lo bf16
__device__ __nv_bfloat16 g_hbf[2][2][(size_t)BATCH * HID];        // h hi/lo bf16 ping-pong
__device__ unsigned g_bar_count;
__device__ unsigned g_bar_phase;

// ---------------- helpers ----------------
__device__ __forceinline__ uint32_t smem_to_u32(const void* p) {
    uint32_t a;
    asm("{ .reg .u64 t; cvta.to.shared.u64 t, %1; cvt.u32.u64 %0, t; }" : "=r"(a) : "l"(p));
    return a;
}
__device__ __forceinline__ uint32_t lds32(uint32_t a) {
    uint32_t v;
    asm volatile("ld.shared.b32 %0, [%1];" : "=r"(v) : "r"(a));
    return v;
}
__device__ __forceinline__ void sts64(uint32_t a, uint32_t v0, uint32_t v1) {
    asm volatile("st.shared.v2.b32 [%0], {%1, %2};" :: "r"(a), "r"(v0), "r"(v1));
}
__device__ __forceinline__ uint32_t ldcg_u32(const void* p) {
    uint32_t v;
    asm volatile("ld.global.cg.u32 %0, [%1];" : "=r"(v) : "l"(p));
    return v;
}
#define CP_ASYNC16(dst, src) \
    asm volatile("cp.async.cg.shared.global [%0], [%1], 16;" :: "r"(dst), "l"(src))
#define CP_COMMIT() asm volatile("cp.async.commit_group;" ::: "memory")
#define CP_WAIT(n)  asm volatile("cp.async.wait_group %0;" :: "n"(n) : "memory")

// bf16 mma: D(16x8 fp32) += A(16x16) * B(16x8)
__device__ __forceinline__ void mma_bf16(float* c, const uint32_t* a, const uint32_t* b) {
    asm volatile(
        "mma.sync.aligned.m16n8k16.row.col.f32.bf16.bf16.f32 "
        "{%0,%1,%2,%3}, {%4,%5,%6,%7}, {%8,%9}, {%0,%1,%2,%3};"
        : "+f"(c[0]), "+f"(c[1]), "+f"(c[2]), "+f"(c[3])
        : "r"(a[0]), "r"(a[1]), "r"(a[2]), "r"(a[3]), "r"(b[0]), "r"(b[1]));
}

__device__ __forceinline__ uint32_t pack_hi2(float x0, float x1) {
    __nv_bfloat162 h = __halves2bfloat162(__float2bfloat16(x0), __float2bfloat16(x1));
    return *(uint32_t*)&h;
}
__device__ __forceinline__ uint32_t pack_lo2(float x0, float x1) {
    __nv_bfloat16 h0 = __float2bfloat16(x0);
    __nv_bfloat16 h1 = __float2bfloat16(x1);
    __nv_bfloat162 l = __halves2bfloat162(
        __float2bfloat16(x0 - __bfloat162float(h0)),
        __float2bfloat16(x1 - __bfloat162float(h1)));
    return *(uint32_t*)&l;
}

// ---------------- zero h0 + barrier reset ----------------
__global__ void zero_h_kernel() {
    int i = blockIdx.x * blockDim.x + threadIdx.x;
    if (i < BATCH * HID) {
        g_hbf[0][0][i] = __float2bfloat16(0.f);
        g_hbf[0][1][i] = __float2bfloat16(0.f);
    }
    if (i == 0) { g_bar_count = 0u; g_bar_phase = 0u; }
}

// ---------------- W split prep: fp32 -> bf16 hi + lo ----------------
__global__ void wprep_kernel(const float* __restrict__ wfr, const float* __restrict__ wgr,
                             const float* __restrict__ wtr,
                             const float* __restrict__ wfi, const float* __restrict__ wgi,
                             const float* __restrict__ wti) {
    int i = blockIdx.x * blockDim.x + threadIdx.x;
    if (i < HID * HID) {
        const float* ws[3] = {wfr, wgr, wtr};
        #pragma unroll
        for (int m = 0; m < 3; m++) {
            float x = ws[m][i];
            __nv_bfloat16 h = __float2bfloat16(x);
            g_wbf[m][0][i] = h;
            g_wbf[m][1][i] = __float2bfloat16(x - __bfloat162float(h));
        }
    }
    if (i < HID * INDIM) {
        const float* ws[3] = {wfi, wgi, wti};
        #pragma unroll
        for (int m = 0; m < 3; m++) {
            float x = ws[m][i];
            __nv_bfloat16 h = __float2bfloat16(x);
            g_wbf_in[m][0][i] = h;
            g_wbf_in[m][1][i] = __float2bfloat16(x - __bfloat162float(h));
        }
    }
}

// =========================================================================
// proj kernel via mma.sync (unchanged from R8): 512 threads, grid (2048, 4)
// =========================================================================
#define NTHREADS 512
#define PITCHB 144
#define A_BYTES (256 * PITCHB)
#define B_BYTES (384 * PITCHB)
#define BUF_BYTES (A_BYTES + B_BYTES)
#define PROJ_SMEM (2 * BUF_BYTES)

#define COMPUTE_CHUNK(bb)                                                        \
    do {                                                                         \
        const uint32_t Abase = sbase + (bb) * BUF_BYTES;                         \
        const uint32_t Bbase = Abase + A_BYTES;                                  \
        _Pragma("unroll")                                                        \
        for (int q = 0; q < 4; q++) {                                            \
            const uint32_t koff = q * 32 + tig * 4;                              \
            uint32_t ahi[2][4], alo[2][4];                                       \
            _Pragma("unroll")                                                    \
            for (int f = 0; f < 2; f++) {                                        \
                uint32_t rh = Abase + (uint32_t)((m0w + f * 16 + group) * PITCHB) + koff; \
                ahi[f][0] = lds32(rh);                                           \
                ahi[f][1] = lds32(rh + 8 * PITCHB);                              \
                ahi[f][2] = lds32(rh + 16);                                      \
                ahi[f][3] = lds32(rh + 8 * PITCHB + 16);                         \
                uint32_t rl = rh + 128 * PITCHB;                                 \
                alo[f][0] = lds32(rl);                                           \
                alo[f][1] = lds32(rl + 8 * PITCHB);                              \
                alo[f][2] = lds32(rl + 16);                                      \
                alo[f][3] = lds32(rl + 8 * PITCHB + 16);                         \
            }                                                                    \
            _Pragma("unroll")                                                    \
            for (int mat = 0; mat < 3; mat++) {                                  \
                uint32_t bh[2][2], bl[2][2];                                     \
                _Pragma("unroll")                                                \
                for (int j = 0; j < 2; j++) {                                    \
                    uint32_t rbh = Bbase +                                       \
                        (uint32_t)(((mat * 2) * 64 + n0w + j * 8 + group) * PITCHB) + koff; \
                    bh[j][0] = lds32(rbh); bh[j][1] = lds32(rbh + 16);           \
                    uint32_t rbl = rbh + 64 * PITCHB;                            \
                    bl[j][0] = lds32(rbl); bl[j][1] = lds32(rbl + 16);           \
                }                                                                \
                _Pragma("unroll")                                                \
                for (int j = 0; j < 2; j++)                                      \
                    { mma_bf16(acc[mat][0][j], ahi[0], bh[j]);                   \
                      mma_bf16(acc[mat][1][j], ahi[1], bh[j]); }                 \
                _Pragma("unroll")                                                \
                for (int j = 0; j < 2; j++)                                      \
                    { mma_bf16(acc[mat][0][j], ahi[0], bl[j]);                   \
                      mma_bf16(acc[mat][1][j], ahi[1], bl[j]); }                 \
                _Pragma("unroll")                                                \
                for (int j = 0; j < 2; j++)                                      \
                    { mma_bf16(acc[mat][0][j], alo[0], bh[j]);                   \
                      mma_bf16(acc[mat][1][j], alo[1], bh[j]); }                 \
            }                                                                    \
        }                                                                        \
    } while (0)

__global__ __launch_bounds__(NTHREADS, 1) void proj_mma_kernel(
    const float* __restrict__ x,
    const float* __restrict__ bfa, const float* __restrict__ bfb,
    const float* __restrict__ bga, const float* __restrict__ bgb,
    const float* __restrict__ bta, const float* __restrict__ btb)
{
    extern __shared__ char sm[];
    const uint32_t sbase = smem_to_u32(sm);

    const int tid   = threadIdx.x;
    const int warp  = tid >> 5;
    const int lane  = tid & 31;
    const int group = lane >> 2;
    const int tig   = lane & 3;
    const int m0    = blockIdx.x * 128;
    const int n0    = blockIdx.y * 64;
    const int m0w   = (warp & 3) * 32;
    const int n0w   = (warp >> 2) * 16;
    const int tq    = m0 >> 12;
    const int bq0   = m0 & 4095;

    float acc[3][2][2][4] = {};

    auto stageA = [&](int chunk, int bb) {
        const uint32_t dstb = sbase + bb * BUF_BYTES;
        #pragma unroll
        for (int j = 0; j < 4; j++) {
            int u   = tid + j * NTHREADS;
            int row = u >> 4;
            int f4  = u & 15;
            float4 v = *(const float4*)&x[((((size_t)(bq0 + row) * 3 + chunk) << 6) + tq) * 64 + f4 * 4];
            uint32_t base = dstb + (uint32_t)(row * PITCHB + f4 * 8);
            sts64(base, pack_hi2(v.x, v.y), pack_hi2(v.z, v.w));
            sts64(base + 128 * PITCHB, pack_lo2(v.x, v.y), pack_lo2(v.z, v.w));
        }
    };
    auto stageB = [&](int chunk, int bb) {
        const int kc0 = chunk * 64;
        const uint32_t dstb = sbase + bb * BUF_BYTES + A_BYTES;
        #pragma unroll
        for (int j = 0; j < 6; j++) {
            int u = tid + j * NTHREADS;
            int rg = u >> 9, row = (u >> 3) & 63, kb = u & 7;
            int mat = rg >> 1, sp = rg & 1;
            const __nv_bfloat16* src =
                &g_wbf_in[mat][sp][(size_t)(n0 + row) * INDIM + kc0 + kb * 8];
            uint32_t dst = dstb + (uint32_t)((rg * 64 + row) * PITCHB + kb * 16);
            CP_ASYNC16(dst, src);
        }
    };

    stageB(0, 0); CP_COMMIT();
    stageA(0, 0);
    #pragma unroll 1
    for (int c = 0; c < 3; c++) {
        if (c < 2) {
            stageB(c + 1, (c + 1) & 1); CP_COMMIT();
            stageA(c + 1, (c + 1) & 1);
            CP_WAIT(1);
        } else {
            CP_WAIT(0);
        }
        __syncthreads();
        COMPUTE_CHUNK(c & 1);
        __syncthreads();
    }

    const float* inb[3]  = {bfa, bga, bta};
    const float* hbb[3]  = {bfb, bgb, btb};
    #pragma unroll
    for (int f = 0; f < 2; f++) {
        #pragma unroll
        for (int hh = 0; hh < 2; hh++) {
            const int m = m0w + f * 16 + group + hh * 8;
            const size_t obase = (size_t)(m0 + m) * HID;
            #pragma unroll
            for (int j = 0; j < 2; j++) {
                const int jabs = n0 + n0w + j * 8 + tig * 2;
                #pragma unroll
                for (int mat = 0; mat < 3; mat++) {
                    float2 bi = *(const float2*)&inb[mat][jabs];
                    float2 bh2 = *(const float2*)&hbb[mat][jabs];
                    float2 o;
                    o.x = acc[mat][f][j][hh * 2]     + bi.x + bh2.x;
                    o.y = acc[mat][f][j][hh * 2 + 1] + bi.y + bh2.y;
                    *(float2*)&g_proj[mat][obase + jabs] = o;
                }
            }
        }
    }
}

// =========================================================================
// persistent recurrence: all 64 steps in one launch, W resident in smem
// grid 128 CTAs (16 b-tiles x 8 n-tiles), 512 threads, 1 CTA/SM (all resident)
// CTA tile: 256 batch rows x 32 out cols x 3 mats
// smem: W 6x16KB swizzled (96KB, loaded once) + A double buffer 2x64KB
// =========================================================================
#define W_SM_BYTES 98304
#define A_SM_BYTES 65536
#define PERS_SMEM (W_SM_BYTES + 2 * A_SM_BYTES + 128)

__global__ __launch_bounds__(NTHREADS, 1) void ltc_persistent_kernel()
{
    extern __shared__ char sm[];
    const uint32_t sW = (smem_to_u32(sm) + 127u) & ~127u;
    const uint32_t sA = sW + W_SM_BYTES;

    const int tid   = threadIdx.x;
    const int warp  = tid >> 5;
    const int lane  = tid & 31;
    const int group = lane >> 2;
    const int tig   = lane & 3;
    const int bx    = blockIdx.x;
    const int b0    = (bx & 15) * 256;
    const int n0    = (bx >> 4) * 32;
    const int m0w   = (warp & 7) * 32;
    const int n0w   = (warp >> 3) * 16;

    // ---- load W once: 6 regions x 32 rows x 512B, XOR-swizzled ----
    #pragma unroll
    for (int j = 0; j < 12; j++) {
        int u   = tid + j * NTHREADS;       // 0..6143 16B units
        int rg  = u >> 10;
        int rem = u & 1023;
        int row = rem >> 5;                 // 0..31
        int kb  = rem & 31;                 // 0..31
        int mat = rg >> 1, sp = rg & 1;
        const __nv_bfloat16* src = &g_wbf[mat][sp][(size_t)(n0 + row) * HID + kb * 8];
        uint32_t dst = sW + (uint32_t)(rg * 16384 + row * 512 + ((kb * 16) ^ ((row & 7) << 4)));
        CP_ASYNC16(dst, src);
    }
    CP_COMMIT(); CP_WAIT(0);
    __syncthreads();

    #pragma unroll 1
    for (int t = 0; t < T; t++) {
        const __nv_bfloat16* __restrict__ hbf_hi = g_hbf[t & 1][0];
        const __nv_bfloat16* __restrict__ hbf_lo = g_hbf[t & 1][1];

        float acc[3][2][2][4] = {};

        auto stageA = [&](int c, int bb) {
            const int kc0 = c * 64;
            const uint32_t dstb = sA + bb * A_SM_BYTES;
            #pragma unroll
            for (int j = 0; j < 8; j++) {
                int u = tid + j * NTHREADS;     // 0..4095 16B units
                int s = u >> 11, row = (u >> 3) & 255, kb = u & 7;
                const __nv_bfloat16* src =
                    (s ? hbf_lo : hbf_hi) + (size_t)(b0 + row) * HID + kc0 + kb * 8;
                uint32_t dst = dstb + (uint32_t)((s * 256 + row) * 128 +
                                                 ((kb * 16) ^ ((row & 7) << 4)));
                CP_ASYNC16(dst, src);
            }
        };

        stageA(0, 0);
        CP_COMMIT();
        #pragma unroll 1
        for (int c = 0; c < 4; c++) {
            if (c < 3) {
                stageA(c + 1, (c + 1) & 1);
                CP_COMMIT();
                CP_WAIT(1);
            } else {
                CP_WAIT(0);
            }
            __syncthreads();
            {
                const uint32_t Ab = sA + (c & 1) * A_SM_BYTES;
                #pragma unroll
                for (int q = 0; q < 4; q++) {
                    const uint32_t pA = (uint32_t)((q * 32 + tig * 4) ^ (group << 4));
                    uint32_t ahi[2][4], alo[2][4];
                    #pragma unroll
                    for (int f = 0; f < 2; f++) {
                        uint32_t rh = Ab + (uint32_t)((m0w + f * 16 + group) * 128) + pA;
                        ahi[f][0] = lds32(rh);        ahi[f][1] = lds32(rh + 1024);
                        ahi[f][2] = lds32(rh ^ 16u);  ahi[f][3] = lds32((rh + 1024) ^ 16u);
                        uint32_t rl = rh + 32768;
                        alo[f][0] = lds32(rl);        alo[f][1] = lds32(rl + 1024);
                        alo[f][2] = lds32(rl ^ 16u);  alo[f][3] = lds32((rl + 1024) ^ 16u);
                    }
                    const uint32_t pB = (uint32_t)((c * 128 + q * 32 + tig * 4) ^ (group << 4));
                    #pragma unroll
                    for (int mat = 0; mat < 3; mat++) {
                        uint32_t bh[2][2], bl[2][2];
                        #pragma unroll
                        for (int j = 0; j < 2; j++) {
                            uint32_t rbh = sW + (uint32_t)(mat * 32768) +
                                           (uint32_t)((n0w + j * 8 + group) * 512) + pB;
                            bh[j][0] = lds32(rbh);  bh[j][1] = lds32(rbh ^ 16u);
                            uint32_t rbl = rbh + 16384;
                            bl[j][0] = lds32(rbl);  bl[j][1] = lds32(rbl ^ 16u);
                        }
                        #pragma unroll
                        for (int j = 0; j < 2; j++)
                            { mma_bf16(acc[mat][0][j], ahi[0], bh[j]);
                              mma_bf16(acc[mat][1][j], ahi[1], bh[j]); }
                        #pragma unroll
                        for (int j = 0; j < 2; j++)
                            { mma_bf16(acc[mat][0][j], ahi[0], bl[j]);
                              mma_bf16(acc[mat][1][j], ahi[1], bl[j]); }
                        #pragma unroll
                        for (int j = 0; j < 2; j++)
                            { mma_bf16(acc[mat][0][j], alo[0], bh[j]);
                              mma_bf16(acc[mat][1][j], alo[1], bh[j]); }
                    }
                }
            }
            __syncthreads();
        }

        // ---- fused LTC epilogue ----
        uint32_t* __restrict__ out_hi = (uint32_t*)g_hbf[(t + 1) & 1][0];
        uint32_t* __restrict__ out_lo = (uint32_t*)g_hbf[(t + 1) & 1][1];
        #pragma unroll
        for (int f = 0; f < 2; f++) {
            #pragma unroll
            for (int hh = 0; hh < 2; hh++) {
                const int r = m0w + f * 16 + group + hh * 8;
                const int b = b0 + r;
                const size_t hrow  = (size_t)b * HID;
                const size_t pbase = ((size_t)t * BATCH + b) * HID;
                #pragma unroll
                for (int j = 0; j < 2; j++) {
                    const int jabs = n0 + n0w + j * 8 + tig * 2;
                    float2 pf = *(const float2*)&g_proj[0][pbase + jabs];
                    float2 pg = *(const float2*)&g_proj[1][pbase + jabs];
                    float2 pt = *(const float2*)&g_proj[2][pbase + jabs];
                    // reconstruct current h (hi+lo), .cg to bypass stale L1
                    uint32_t hib = ldcg_u32(&hbf_hi[hrow + jabs]);
                    uint32_t lob = ldcg_u32(&hbf_lo[hrow + jabs]);
                    __nv_bfloat162 hi2 = *(__nv_bfloat162*)&hib;
                    __nv_bfloat162 lo2 = *(__nv_bfloat162*)&lob;
                    float hv[2] = {__bfloat162float(hi2.x) + __bfloat162float(lo2.x),
                                   __bfloat162float(hi2.y) + __bfloat162float(lo2.y)};
                    float o2[2];
                    #pragma unroll
                    for (int e = 0; e < 2; e++) {
                        float rf = acc[0][f][j][hh * 2 + e];
                        float rg = acc[1][f][j][hh * 2 + e];
                        float rt = acc[2][f][j][hh * 2 + e];
                        float pfe = e ? pf.y : pf.x;
                        float pge = e ? pg.y : pg.x;
                        float pte = e ? pt.y : pt.x;
                        float e2 = __expf(2.f * (pfe + rf));
                        float cand = (e2 - 1.f) / (e2 + 1.f);
                        float gate = 1.f / (1.f + __expf(-(pge + rg)));
                        float tau  = 0.5f + 1.5f / (1.f + __expf(-(pte + rt)));
                        float hn = hv[e] + (gate * cand - hv[e]) / tau;
                        float e2h = __expf(2.f * hn);
                        o2[e] = (e2h - 1.f) / (e2h + 1.f);
                    }
                    out_hi[hrow + jabs >> 1 << 0] = 0;  // placeholder removed below
                }
            }
        }
        // NOTE: the loop above is re-run with correct stores (see below)
        // -- real epilogue stores --
        #pragma unroll
        for (int f = 0; f < 2; f++) {
            #pragma unroll
            for (int hh = 0; hh < 2; hh++) {
                const int r = m0w + f * 16 + group + hh * 8;
                const int b = b0 + r;
                const size_t hrow  = (size_t)b * HID;
                const size_t pbase = ((size_t)t * BATCH + b) * HID;
                #pragma unroll
                for (int j = 0; j < 2; j++) {
                    const int jabs = n0 + n0w + j * 8 + tig * 2;
                    float2 pf = *(const float2*)&g_proj[0][pbase + jabs];
                    float2 pg = *(const float2*)&g_proj[1][pbase + jabs];
                    float2 pt = *(const float2*)&g_proj[2][pbase + jabs];
                    uint32_t hib = ldcg_u32(&hbf_hi[hrow + jabs]);
                    uint32_t lob = ldcg_u32(&hbf_lo[hrow + jabs]);
                    __nv_bfloat162 hi2 = *(__nv_bfloat162*)&hib;
                    __nv_bfloat162 lo2 = *(__nv_bfloat162*)&lob;
                    float hv[2] = {__bfloat162float(hi2.x) + __bfloat162float(lo2.x),
                                   __bfloat162float(hi2.y) + __bfloat162float(lo2.y)};
                    float o2[2];
                    #pragma unroll
                    for (int e = 0; e < 2; e++) {
                        float rf = acc[0][f][j][hh * 2 + e];
                        float rg = acc[1][f][j][hh * 2 + e];
                        float rt = acc[2][f][j][hh * 2 + e];
                        float pfe = e ? pf.y : pf.x;
                        float pge = e ? pg.y : pg.x;
                        float pte = e ? pt.y : pt.x;
                        float hve = hv[e];
                        float e2 = __expf(2.f * (pfe + rf));
                        float cand = (e2 - 1.f) / (e2 + 1.f);
                        float gate = 1.f / (1.f + __expf(-(pge + rg)));
                        float tau  = 0.5f + 1.5f / (1.f + __expf(-(pte + rt)));
                        float hn = hve + (gate * cand - hve) / tau;
                        float e2h = __expf(2.f * hn);
                        o2[e] = (e2h - 1.f) / (e2h + 1.f);
                    }
                    *(uint32_t*)((char*)out_hi + (hrow + jabs) * 2) = pack_hi2(o2[0], o2[1]);
                    *(uint32_t*)((char*)out_lo + (hrow + jabs) * 2) = pack_lo2(o2[0], o2[1]);
                }
            }
        }

        // ---- device-wide barrier (skip after last step) ----
        if (t < T - 1) {
            __threadfence();
            __syncthreads();
            if (tid == 0) {
                unsigned need = (unsigned)(t + 1) * (unsigned)NCTA;
                unsigned arrived = atomicAdd(&g_bar_count, 1u) + 1u;
                if (arrived == need) {
                    atomicExch(&g_bar_phase, (unsigned)(t + 1));
                } else {
                    while (ldcg_u32(&g_bar_phase) < (unsigned)(t + 1)) __nanosleep(64);
                }
                __threadfence();
            }
            __syncthreads();
        }
    }
}

// ---------------- head: h reconstructed from bf16 hi/lo ----------------
__global__ void head_kernel(const float* __restrict__ hw,
                            const float* __restrict__ hb,
                            float* __restrict__ out)
{
    int gwarp = (blockIdx.x * blockDim.x + threadIdx.x) >> 5;
    int lane  = threadIdx.x & 31;
    if (gwarp >= BATCH * 10) return;
    int o = gwarp % 10;
    int b = gwarp / 10;
    const __nv_bfloat16* hhi = g_hbf[0][0];   // T=64 even -> final state parity 0
    const __nv_bfloat16* hlo = g_hbf[0][1];
    float s = 0.f;
    #pragma unroll
    for (int k = lane; k < HID; k += 32) {
        float hv = __bfloat162float(hhi[(size_t)b * HID + k]) +
                   __bfloat162float(hlo[(size_t)b * HID + k]);
        s += hv * hw[o * HID + k];
    }
    #pragma unroll
    for (int off = 16; off; off >>= 1)
        s += __shfl_down_sync(0xffffffffu, s, off);
    if (lane == 0) out[b * 10 + o] = s + hb[o];
}

extern "C" void kernel_launch(void* const* d_in, const int* in_sizes, int n_in,
                              void* d_out, int out_size)
{
    const float* x      = (const float*)d_in[0];
    const float* ffw    = (const float*)d_in[1];
    const float* ffb    = (const float*)d_in[2];
    const float* ffrw   = (const float*)d_in[3];
    const float* ffbias = (const float*)d_in[4];
    const float* gw     = (const float*)d_in[5];
    const float* gb     = (const float*)d_in[6];
    const float* grw    = (const float*)d_in[7];
    const float* gbias  = (const float*)d_in[8];
    const float* tw     = (const float*)d_in[9];
    const float* tb     = (const float*)d_in[10];
    const float* trw    = (const float*)d_in[11];
    const float* tbias  = (const float*)d_in[12];
    const float* hw     = (const float*)d_in[13];
    const float* hb     = (const float*)d_in[14];
    float* out = (float*)d_out;

    cudaFuncSetAttribute(proj_mma_kernel,
                         cudaFuncAttributeMaxDynamicSharedMemorySize, PROJ_SMEM);
    cudaFuncSetAttribute(ltc_persistent_kernel,
                         cudaFuncAttributeMaxDynamicSharedMemorySize, PERS_SMEM);

    // h0 = 0 + barrier counters reset (every replay)
    zero_h_kernel<<<(BATCH * HID + 255) / 256, 256>>>();

    // W (recurrent + input) -> bf16 hi/lo scratch
    wprep_kernel<<<(HID * HID + 255) / 256, 256>>>(ffrw, grw, trw, ffw, gw, tw);

    // all input projections on the tensor pipe
    dim3 pgrid((T * BATCH) / 128, HID / 64);
    proj_mma_kernel<<<pgrid, NTHREADS, PROJ_SMEM>>>(x, ffb, ffbias, gb, gbias, tb, tbias);

    // all 64 LTC steps in one persistent kernel (W resident in smem)
    ltc_persistent_kernel<<<NCTA, NTHREADS, PERS_SMEM>>>();

    // classifier head
    head_kernel<<<(BATCH * 10 * 32 + 255) / 256, 256>>>(hw, hb, out);
}

// round 10
// speedup vs baseline: 1.0281x; 1.0281x over previous
#include <cuda_runtime.h>
#include <cuda_bf16.h>
#include <math.h>
#include <cstdint>

#define BATCH 4096
#define T 64
#define HID 256
#define INDIM 192
#define NCTA 128

// ---------------- device scratch ----------------
__device__ float g_proj[3][(size_t)T * BATCH * HID];              // input projections
__device__ __nv_bfloat16 g_wbf[3][2][HID * HID];                  // W_rec hi/lo bf16
__device__ __nv_bfloat16 g_wbf_in[3][2][HID * INDIM];             // W_in hi/lo bf16
__device__ __nv_bfloat16 g_hbf[2][2][(size_t)BATCH * HID];        // h hi/lo bf16 ping-pong
__device__ unsigned g_bar_count;
__device__ unsigned g_bar_phase;

// ---------------- helpers ----------------
__device__ __forceinline__ uint32_t smem_to_u32(const void* p) {
    uint32_t a;
    asm("{ .reg .u64 t; cvta.to.shared.u64 t, %1; cvt.u32.u64 %0, t; }" : "=r"(a) : "l"(p));
    return a;
}
__device__ __forceinline__ uint32_t lds32(uint32_t a) {
    uint32_t v;
    asm volatile("ld.shared.b32 %0, [%1];" : "=r"(v) : "r"(a));
    return v;
}
__device__ __forceinline__ void sts64(uint32_t a, uint32_t v0, uint32_t v1) {
    asm volatile("st.shared.v2.b32 [%0], {%1, %2};" :: "r"(a), "r"(v0), "r"(v1));
}
__device__ __forceinline__ uint32_t ldcg_u32(const void* p) {
    uint32_t v;
    asm volatile("ld.global.cg.u32 %0, [%1];" : "=r"(v) : "l"(p));
    return v;
}
#define CP_ASYNC16(dst, src) \
    asm volatile("cp.async.cg.shared.global [%0], [%1], 16;" :: "r"(dst), "l"(src))
#define CP_COMMIT() asm volatile("cp.async.commit_group;" ::: "memory")
#define CP_WAIT(n)  asm volatile("cp.async.wait_group %0;" :: "n"(n) : "memory")

// bf16 mma: D(16x8 fp32) += A(16x16) * B(16x8)
__device__ __forceinline__ void mma_bf16(float* c, const uint32_t* a, const uint32_t* b) {
    asm volatile(
        "mma.sync.aligned.m16n8k16.row.col.f32.bf16.bf16.f32 "
        "{%0,%1,%2,%3}, {%4,%5,%6,%7}, {%8,%9}, {%0,%1,%2,%3};"
        : "+f"(c[0]), "+f"(c[1]), "+f"(c[2]), "+f"(c[3])
        : "r"(a[0]), "r"(a[1]), "r"(a[2]), "r"(a[3]), "r"(b[0]), "r"(b[1]));
}

__device__ __forceinline__ uint32_t pack_hi2(float x0, float x1) {
    __nv_bfloat162 h = __halves2bfloat162(__float2bfloat16(x0), __float2bfloat16(x1));
    return *(uint32_t*)&h;
}
__device__ __forceinline__ uint32_t pack_lo2(float x0, float x1) {
    __nv_bfloat16 h0 = __float2bfloat16(x0);
    __nv_bfloat16 h1 = __float2bfloat16(x1);
    __nv_bfloat162 l = __halves2bfloat162(
        __float2bfloat16(x0 - __bfloat162float(h0)),
        __float2bfloat16(x1 - __bfloat162float(h1)));
    return *(uint32_t*)&l;
}

// ---------------- zero h0 + barrier reset ----------------
__global__ void zero_h_kernel() {
    int i = blockIdx.x * blockDim.x + threadIdx.x;
    if (i < BATCH * HID) {
        g_hbf[0][0][i] = __float2bfloat16(0.f);
        g_hbf[0][1][i] = __float2bfloat16(0.f);
    }
    if (i == 0) { g_bar_count = 0u; g_bar_phase = 0u; }
}

// ---------------- W split prep: fp32 -> bf16 hi + lo ----------------
__global__ void wprep_kernel(const float* __restrict__ wfr, const float* __restrict__ wgr,
                             const float* __restrict__ wtr,
                             const float* __restrict__ wfi, const float* __restrict__ wgi,
                             const float* __restrict__ wti) {
    int i = blockIdx.x * blockDim.x + threadIdx.x;
    if (i < HID * HID) {
        const float* ws[3] = {wfr, wgr, wtr};
        #pragma unroll
        for (int m = 0; m < 3; m++) {
            float x = ws[m][i];
            __nv_bfloat16 h = __float2bfloat16(x);
            g_wbf[m][0][i] = h;
            g_wbf[m][1][i] = __float2bfloat16(x - __bfloat162float(h));
        }
    }
    if (i < HID * INDIM) {
        const float* ws[3] = {wfi, wgi, wti};
        #pragma unroll
        for (int m = 0; m < 3; m++) {
            float x = ws[m][i];
            __nv_bfloat16 h = __float2bfloat16(x);
            g_wbf_in[m][0][i] = h;
            g_wbf_in[m][1][i] = __float2bfloat16(x - __bfloat162float(h));
        }
    }
}

// =========================================================================
// proj kernel via mma.sync (unchanged): 512 threads, grid (2048, 4)
// =========================================================================
#define NTHREADS 512
#define PITCHB 144
#define A_BYTES (256 * PITCHB)
#define B_BYTES (384 * PITCHB)
#define BUF_BYTES (A_BYTES + B_BYTES)
#define PROJ_SMEM (2 * BUF_BYTES)

#define COMPUTE_CHUNK(bb)                                                        \
    do {                                                                         \
        const uint32_t Abase = sbase + (bb) * BUF_BYTES;                         \
        const uint32_t Bbase = Abase + A_BYTES;                                  \
        _Pragma("unroll")                                                        \
        for (int q = 0; q < 4; q++) {                                            \
            const uint32_t koff = q * 32 + tig * 4;                              \
            uint32_t ahi[2][4], alo[2][4];                                       \
            _Pragma("unroll")                                                    \
            for (int f = 0; f < 2; f++) {                                        \
                uint32_t rh = Abase + (uint32_t)((m0w + f * 16 + group) * PITCHB) + koff; \
                ahi[f][0] = lds32(rh);                                           \
                ahi[f][1] = lds32(rh + 8 * PITCHB);                              \
                ahi[f][2] = lds32(rh + 16);                                      \
                ahi[f][3] = lds32(rh + 8 * PITCHB + 16);                         \
                uint32_t rl = rh + 128 * PITCHB;                                 \
                alo[f][0] = lds32(rl);                                           \
                alo[f][1] = lds32(rl + 8 * PITCHB);                              \
                alo[f][2] = lds32(rl + 16);                                      \
                alo[f][3] = lds32(rl + 8 * PITCHB + 16);                         \
            }                                                                    \
            _Pragma("unroll")                                                    \
            for (int mat = 0; mat < 3; mat++) {                                  \
                uint32_t bh[2][2], bl[2][2];                                     \
                _Pragma("unroll")                                                \
                for (int j = 0; j < 2; j++) {                                    \
                    uint32_t rbh = Bbase +                                       \
                        (uint32_t)(((mat * 2) * 64 + n0w + j * 8 + group) * PITCHB) + koff; \
                    bh[j][0] = lds32(rbh); bh[j][1] = lds32(rbh + 16);           \
                    uint32_t rbl = rbh + 64 * PITCHB;                            \
                    bl[j][0] = lds32(rbl); bl[j][1] = lds32(rbl + 16);           \
                }                                                                \
                _Pragma("unroll")                                                \
                for (int j = 0; j < 2; j++)                                      \
                    { mma_bf16(acc[mat][0][j], ahi[0], bh[j]);                   \
                      mma_bf16(acc[mat][1][j], ahi[1], bh[j]); }                 \
                _Pragma("unroll")                                                \
                for (int j = 0; j < 2; j++)                                      \
                    { mma_bf16(acc[mat][0][j], ahi[0], bl[j]);                   \
                      mma_bf16(acc[mat][1][j], ahi[1], bl[j]); }                 \
                _Pragma("unroll")                                                \
                for (int j = 0; j < 2; j++)                                      \
                    { mma_bf16(acc[mat][0][j], alo[0], bh[j]);                   \
                      mma_bf16(acc[mat][1][j], alo[1], bh[j]); }                 \
            }                                                                    \
        }                                                                        \
    } while (0)

__global__ __launch_bounds__(NTHREADS, 1) void proj_mma_kernel(
    const float* __restrict__ x,
    const float* __restrict__ bfa, const float* __restrict__ bfb,
    const float* __restrict__ bga, const float* __restrict__ bgb,
    const float* __restrict__ bta, const float* __restrict__ btb)
{
    extern __shared__ char sm[];
    const uint32_t sbase = smem_to_u32(sm);

    const int tid   = threadIdx.x;
    const int warp  = tid >> 5;
    const int lane  = tid & 31;
    const int group = lane >> 2;
    const int tig   = lane & 3;
    const int m0    = blockIdx.x * 128;
    const int n0    = blockIdx.y * 64;
    const int m0w   = (warp & 3) * 32;
    const int n0w   = (warp >> 2) * 16;
    const int tq    = m0 >> 12;
    const int bq0   = m0 & 4095;

    float acc[3][2][2][4] = {};

    auto stageA = [&](int chunk, int bb) {
        const uint32_t dstb = sbase + bb * BUF_BYTES;
        #pragma unroll
        for (int j = 0; j < 4; j++) {
            int u   = tid + j * NTHREADS;
            int row = u >> 4;
            int f4  = u & 15;
            float4 v = *(const float4*)&x[((((size_t)(bq0 + row) * 3 + chunk) << 6) + tq) * 64 + f4 * 4];
            uint32_t base = dstb + (uint32_t)(row * PITCHB + f4 * 8);
            sts64(base, pack_hi2(v.x, v.y), pack_hi2(v.z, v.w));
            sts64(base + 128 * PITCHB, pack_lo2(v.x, v.y), pack_lo2(v.z, v.w));
        }
    };
    auto stageB = [&](int chunk, int bb) {
        const int kc0 = chunk * 64;
        const uint32_t dstb = sbase + bb * BUF_BYTES + A_BYTES;
        #pragma unroll
        for (int j = 0; j < 6; j++) {
            int u = tid + j * NTHREADS;
            int rg = u >> 9, row = (u >> 3) & 63, kb = u & 7;
            int mat = rg >> 1, sp = rg & 1;
            const __nv_bfloat16* src =
                &g_wbf_in[mat][sp][(size_t)(n0 + row) * INDIM + kc0 + kb * 8];
            uint32_t dst = dstb + (uint32_t)((rg * 64 + row) * PITCHB + kb * 16);
            CP_ASYNC16(dst, src);
        }
    };

    stageB(0, 0); CP_COMMIT();
    stageA(0, 0);
    #pragma unroll 1
    for (int c = 0; c < 3; c++) {
        if (c < 2) {
            stageB(c + 1, (c + 1) & 1); CP_COMMIT();
            stageA(c + 1, (c + 1) & 1);
            CP_WAIT(1);
        } else {
            CP_WAIT(0);
        }
        __syncthreads();
        COMPUTE_CHUNK(c & 1);
        __syncthreads();
    }

    const float* inb[3]  = {bfa, bga, bta};
    const float* hbb[3]  = {bfb, bgb, btb};
    #pragma unroll
    for (int f = 0; f < 2; f++) {
        #pragma unroll
        for (int hh = 0; hh < 2; hh++) {
            const int m = m0w + f * 16 + group + hh * 8;
            const size_t obase = (size_t)(m0 + m) * HID;
            #pragma unroll
            for (int j = 0; j < 2; j++) {
                const int jabs = n0 + n0w + j * 8 + tig * 2;
                #pragma unroll
                for (int mat = 0; mat < 3; mat++) {
                    float2 bi = *(const float2*)&inb[mat][jabs];
                    float2 bh2 = *(const float2*)&hbb[mat][jabs];
                    float2 o;
                    o.x = acc[mat][f][j][hh * 2]     + bi.x + bh2.x;
                    o.y = acc[mat][f][j][hh * 2 + 1] + bi.y + bh2.y;
                    *(float2*)&g_proj[mat][obase + jabs] = o;
                }
            }
        }
    }
}

// =========================================================================
// persistent recurrence: all 64 steps in one launch, W resident in smem,
// h epilogue state carried in REGISTERS across steps.
// grid 128 CTAs (16 b-tiles x 8 n-tiles), 512 threads, 1 CTA/SM
// =========================================================================
#define W_SM_BYTES 98304
#define A_SM_BYTES 65536
#define PERS_SMEM (W_SM_BYTES + 2 * A_SM_BYTES + 128)

__global__ __launch_bounds__(NTHREADS, 1) void ltc_persistent_kernel()
{
    extern __shared__ char sm[];
    const uint32_t sW = (smem_to_u32(sm) + 127u) & ~127u;
    const uint32_t sA = sW + W_SM_BYTES;

    const int tid   = threadIdx.x;
    const int warp  = tid >> 5;
    const int lane  = tid & 31;
    const int group = lane >> 2;
    const int tig   = lane & 3;
    const int bx    = blockIdx.x;
    const int b0    = (bx & 15) * 256;
    const int n0    = (bx >> 4) * 32;
    const int m0w   = (warp & 7) * 32;
    const int n0w   = (warp >> 3) * 16;

    // ---- load W once: 6 regions x 32 rows x 512B, XOR-swizzled ----
    #pragma unroll
    for (int j = 0; j < 12; j++) {
        int u   = tid + j * NTHREADS;
        int rg  = u >> 10;
        int rem = u & 1023;
        int row = rem >> 5;
        int kb  = rem & 31;
        int mat = rg >> 1, sp = rg & 1;
        const __nv_bfloat16* src = &g_wbf[mat][sp][(size_t)(n0 + row) * HID + kb * 8];
        uint32_t dst = sW + (uint32_t)(rg * 16384 + row * 512 + ((kb * 16) ^ ((row & 7) << 4)));
        CP_ASYNC16(dst, src);
    }
    CP_COMMIT(); CP_WAIT(0);
    __syncthreads();

    // h state for this thread's epilogue tile, carried in fp32 registers.
    // index [f][hh][j][e] -> b = b0+m0w+f*16+group+hh*8, col = n0+n0w+j*8+tig*2+e
    float hvreg[2][2][2][2] = {};

    #pragma unroll 1
    for (int t = 0; t < T; t++) {
        const __nv_bfloat16* __restrict__ hbf_hi = g_hbf[t & 1][0];
        const __nv_bfloat16* __restrict__ hbf_lo = g_hbf[t & 1][1];

        float acc[3][2][2][4] = {};

        auto stageA = [&](int c, int bb) {
            const int kc0 = c * 64;
            const uint32_t dstb = sA + bb * A_SM_BYTES;
            #pragma unroll
            for (int j = 0; j < 8; j++) {
                int u = tid + j * NTHREADS;
                int s = u >> 11, row = (u >> 3) & 255, kb = u & 7;
                const __nv_bfloat16* src =
                    (s ? hbf_lo : hbf_hi) + (size_t)(b0 + row) * HID + kc0 + kb * 8;
                uint32_t dst = dstb + (uint32_t)((s * 256 + row) * 128 +
                                                 ((kb * 16) ^ ((row & 7) << 4)));
                CP_ASYNC16(dst, src);
            }
        };

        stageA(0, 0);
        CP_COMMIT();
        #pragma unroll 1
        for (int c = 0; c < 4; c++) {
            if (c < 3) {
                stageA(c + 1, (c + 1) & 1);
                CP_COMMIT();
                CP_WAIT(1);
            } else {
                CP_WAIT(0);
            }
            __syncthreads();
            {
                const uint32_t Ab = sA + (c & 1) * A_SM_BYTES;
                #pragma unroll
                for (int q = 0; q < 4; q++) {
                    const uint32_t pA = (uint32_t)((q * 32 + tig * 4) ^ (group << 4));
                    uint32_t ahi[2][4], alo[2][4];
                    #pragma unroll
                    for (int f = 0; f < 2; f++) {
                        uint32_t rh = Ab + (uint32_t)((m0w + f * 16 + group) * 128) + pA;
                        ahi[f][0] = lds32(rh);        ahi[f][1] = lds32(rh + 1024);
                        ahi[f][2] = lds32(rh ^ 16u);  ahi[f][3] = lds32((rh + 1024) ^ 16u);
                        uint32_t rl = rh + 32768;
                        alo[f][0] = lds32(rl);        alo[f][1] = lds32(rl + 1024);
                        alo[f][2] = lds32(rl ^ 16u);  alo[f][3] = lds32((rl + 1024) ^ 16u);
                    }
                    const uint32_t pB = (uint32_t)((c * 128 + q * 32 + tig * 4) ^ (group << 4));
                    #pragma unroll
                    for (int mat = 0; mat < 3; mat++) {
                        uint32_t bh[2][2], bl[2][2];
                        #pragma unroll
                        for (int j = 0; j < 2; j++) {
                            uint32_t rbh = sW + (uint32_t)(mat * 32768) +
                                           (uint32_t)((n0w + j * 8 + group) * 512) + pB;
                            bh[j][0] = lds32(rbh);  bh[j][1] = lds32(rbh ^ 16u);
                            uint32_t rbl = rbh + 16384;
                            bl[j][0] = lds32(rbl);  bl[j][1] = lds32(rbl ^ 16u);
                        }
                        #pragma unroll
                        for (int j = 0; j < 2; j++)
                            { mma_bf16(acc[mat][0][j], ahi[0], bh[j]);
                              mma_bf16(acc[mat][1][j], ahi[1], bh[j]); }
                        #pragma unroll
                        for (int j = 0; j < 2; j++)
                            { mma_bf16(acc[mat][0][j], ahi[0], bl[j]);
                              mma_bf16(acc[mat][1][j], ahi[1], bl[j]); }
                        #pragma unroll
                        for (int j = 0; j < 2; j++)
                            { mma_bf16(acc[mat][0][j], alo[0], bh[j]);
                              mma_bf16(acc[mat][1][j], alo[1], bh[j]); }
                    }
                }
            }
            __syncthreads();
        }

        // ---- fused LTC epilogue (h state in registers) ----
        uint32_t* __restrict__ out_hi = (uint32_t*)g_hbf[(t + 1) & 1][0];
        uint32_t* __restrict__ out_lo = (uint32_t*)g_hbf[(t + 1) & 1][1];
        #pragma unroll
        for (int f = 0; f < 2; f++) {
            #pragma unroll
            for (int hh = 0; hh < 2; hh++) {
                const int r = m0w + f * 16 + group + hh * 8;
                const int b = b0 + r;
                const size_t hrow  = (size_t)b * HID;
                const size_t pbase = ((size_t)t * BATCH + b) * HID;
                #pragma unroll
                for (int j = 0; j < 2; j++) {
                    const int jabs = n0 + n0w + j * 8 + tig * 2;
                    float2 pf = *(const float2*)&g_proj[0][pbase + jabs];
                    float2 pg = *(const float2*)&g_proj[1][pbase + jabs];
                    float2 pt = *(const float2*)&g_proj[2][pbase + jabs];
                    float o2[2];
                    #pragma unroll
                    for (int e = 0; e < 2; e++) {
                        float rf = acc[0][f][j][hh * 2 + e];
                        float rg = acc[1][f][j][hh * 2 + e];
                        float rt = acc[2][f][j][hh * 2 + e];
                        float pfe = e ? pf.y : pf.x;
                        float pge = e ? pg.y : pg.x;
                        float pte = e ? pt.y : pt.x;
                        float hve = hvreg[f][hh][j][e];
                        float e2 = __expf(2.f * (pfe + rf));
                        float cand = (e2 - 1.f) / (e2 + 1.f);
                        float gate = 1.f / (1.f + __expf(-(pge + rg)));
                        float tau  = 0.5f + 1.5f / (1.f + __expf(-(pte + rt)));
                        float hn = hve + (gate * cand - hve) / tau;
                        float e2h = __expf(2.f * hn);
                        o2[e] = (e2h - 1.f) / (e2h + 1.f);
                        hvreg[f][hh][j][e] = o2[e];
                    }
                    *(uint32_t*)((char*)out_hi + (hrow + jabs) * 2) = pack_hi2(o2[0], o2[1]);
                    *(uint32_t*)((char*)out_lo + (hrow + jabs) * 2) = pack_lo2(o2[0], o2[1]);
                }
            }
        }

        // ---- device-wide barrier (skip after last step) ----
        if (t < T - 1) {
            __threadfence();
            __syncthreads();
            if (tid == 0) {
                unsigned need = (unsigned)(t + 1) * (unsigned)NCTA;
                unsigned arrived = atomicAdd(&g_bar_count, 1u) + 1u;
                if (arrived == need) {
                    atomicExch(&g_bar_phase, (unsigned)(t + 1));
                } else {
                    while (ldcg_u32(&g_bar_phase) < (unsigned)(t + 1)) __nanosleep(64);
                }
                __threadfence();
            }
            __syncthreads();
        }
    }
}

// ---------------- head: h reconstructed from bf16 hi/lo ----------------
__global__ void head_kernel(const float* __restrict__ hw,
                            const float* __restrict__ hb,
                            float* __restrict__ out)
{
    int gwarp = (blockIdx.x * blockDim.x + threadIdx.x) >> 5;
    int lane  = threadIdx.x & 31;
    if (gwarp >= BATCH * 10) return;
    int o = gwarp % 10;
    int b = gwarp / 10;
    const __nv_bfloat16* hhi = g_hbf[0][0];   // T=64 even -> final state parity 0
    const __nv_bfloat16* hlo = g_hbf[0][1];
    float s = 0.f;
    #pragma unroll
    for (int k = lane; k < HID; k += 32) {
        float hv = __bfloat162float(hhi[(size_t)b * HID + k]) +
                   __bfloat162float(hlo[(size_t)b * HID + k]);
        s += hv * hw[o * HID + k];
    }
    #pragma unroll
    for (int off = 16; off; off >>= 1)
        s += __shfl_down_sync(0xffffffffu, s, off);
    if (lane == 0) out[b * 10 + o] = s + hb[o];
}

extern "C" void kernel_launch(void* const* d_in, const int* in_sizes, int n_in,
                              void* d_out, int out_size)
{
    const float* x      = (const float*)d_in[0];
    const float* ffw    = (const float*)d_in[1];
    const float* ffb    = (const float*)d_in[2];
    const float* ffrw   = (const float*)d_in[3];
    const float* ffbias = (const float*)d_in[4];
    const float* gw     = (const float*)d_in[5];
    const float* gb     = (const float*)d_in[6];
    const float* grw    = (const float*)d_in[7];
    const float* gbias  = (const float*)d_in[8];
    const float* tw     = (const float*)d_in[9];
    const float* tb     = (const float*)d_in[10];
    const float* trw    = (const float*)d_in[11];
    const float* tbias  = (const float*)d_in[12];
    const float* hw     = (const float*)d_in[13];
    const float* hb     = (const float*)d_in[14];
    float* out = (float*)d_out;

    cudaFuncSetAttribute(proj_mma_kernel,
                         cudaFuncAttributeMaxDynamicSharedMemorySize, PROJ_SMEM);
    cudaFuncSetAttribute(ltc_persistent_kernel,
                         cudaFuncAttributeMaxDynamicSharedMemorySize, PERS_SMEM);

    // h0 = 0 + barrier counters reset (every replay)
    zero_h_kernel<<<(BATCH * HID + 255) / 256, 256>>>();

    // W (recurrent + input) -> bf16 hi/lo scratch
    wprep_kernel<<<(HID * HID + 255) / 256, 256>>>(ffrw, grw, trw, ffw, gw, tw);

    // all input projections on the tensor pipe
    dim3 pgrid((T * BATCH) / 128, HID / 64);
    proj_mma_kernel<<<pgrid, NTHREADS, PROJ_SMEM>>>(x, ffb, ffbias, gb, gbias, tb, tbias);

    // all 64 LTC steps in one persistent kernel (W resident, h in registers)
    ltc_persistent_kernel<<<NCTA, NTHREADS, PERS_SMEM>>>();

    // classifier head
    head_kernel<<<(BATCH * 10 * 32 + 255) / 256, 256>>>(hw, hb, out);
}

// round 11
// speedup vs baseline: 1.0963x; 1.0663x over previous
#include <cuda_runtime.h>
#include <cuda_bf16.h>
#include <math.h>
#include <cstdint>

#define BATCH 4096
#define T 64
#define HID 256
#define INDIM 192
#define NCTA 128

// ---------------- device scratch ----------------
__device__ float g_proj[3][(size_t)T * BATCH * HID];              // input projections
__device__ __nv_bfloat16 g_wbf[3][2][HID * HID];                  // W_rec hi/lo bf16
__device__ __nv_bfloat16 g_wbf_in[3][2][HID * INDIM];             // W_in hi/lo bf16
__device__ __nv_bfloat16 g_hbf[2][2][(size_t)BATCH * HID];        // h hi/lo bf16 ping-pong
__device__ unsigned g_bar_count;
__device__ unsigned g_bar_phase;

// ---------------- helpers ----------------
__device__ __forceinline__ uint32_t smem_to_u32(const void* p) {
    uint32_t a;
    asm("{ .reg .u64 t; cvta.to.shared.u64 t, %1; cvt.u32.u64 %0, t; }" : "=r"(a) : "l"(p));
    return a;
}
__device__ __forceinline__ uint32_t lds32(uint32_t a) {
    uint32_t v;
    asm volatile("ld.shared.b32 %0, [%1];" : "=r"(v) : "r"(a));
    return v;
}
__device__ __forceinline__ void sts64(uint32_t a, uint32_t v0, uint32_t v1) {
    asm volatile("st.shared.v2.b32 [%0], {%1, %2};" :: "r"(a), "r"(v0), "r"(v1));
}
__device__ __forceinline__ uint32_t ldcg_u32(const void* p) {
    uint32_t v;
    asm volatile("ld.global.cg.u32 %0, [%1];" : "=r"(v) : "l"(p));
    return v;
}
#define CP_ASYNC16(dst, src) \
    asm volatile("cp.async.cg.shared.global [%0], [%1], 16;" :: "r"(dst), "l"(src))
#define CP_COMMIT() asm volatile("cp.async.commit_group;" ::: "memory")
#define CP_WAIT(n)  asm volatile("cp.async.wait_group %0;" :: "n"(n) : "memory")

// bf16 mma: D(16x8 fp32) += A(16x16) * B(16x8)
__device__ __forceinline__ void mma_bf16(float* c, const uint32_t* a, const uint32_t* b) {
    asm volatile(
        "mma.sync.aligned.m16n8k16.row.col.f32.bf16.bf16.f32 "
        "{%0,%1,%2,%3}, {%4,%5,%6,%7}, {%8,%9}, {%0,%1,%2,%3};"
        : "+f"(c[0]), "+f"(c[1]), "+f"(c[2]), "+f"(c[3])
        : "r"(a[0]), "r"(a[1]), "r"(a[2]), "r"(a[3]), "r"(b[0]), "r"(b[1]));
}

__device__ __forceinline__ uint32_t pack_hi2(float x0, float x1) {
    __nv_bfloat162 h = __halves2bfloat162(__float2bfloat16(x0), __float2bfloat16(x1));
    return *(uint32_t*)&h;
}
__device__ __forceinline__ uint32_t pack_lo2(float x0, float x1) {
    __nv_bfloat16 h0 = __float2bfloat16(x0);
    __nv_bfloat16 h1 = __float2bfloat16(x1);
    __nv_bfloat162 l = __halves2bfloat162(
        __float2bfloat16(x0 - __bfloat162float(h0)),
        __float2bfloat16(x1 - __bfloat162float(h1)));
    return *(uint32_t*)&l;
}

// ---------------- zero h0 + barrier reset ----------------
__global__ void zero_h_kernel() {
    int i = blockIdx.x * blockDim.x + threadIdx.x;
    if (i < BATCH * HID) {
        g_hbf[0][0][i] = __float2bfloat16(0.f);
        g_hbf[0][1][i] = __float2bfloat16(0.f);
    }
    if (i == 0) { g_bar_count = 0u; g_bar_phase = 0u; }
}

// ---------------- W split prep: fp32 -> bf16 hi + lo ----------------
__global__ void wprep_kernel(const float* __restrict__ wfr, const float* __restrict__ wgr,
                             const float* __restrict__ wtr,
                             const float* __restrict__ wfi, const float* __restrict__ wgi,
                             const float* __restrict__ wti) {
    int i = blockIdx.x * blockDim.x + threadIdx.x;
    if (i < HID * HID) {
        const float* ws[3] = {wfr, wgr, wtr};
        #pragma unroll
        for (int m = 0; m < 3; m++) {
            float x = ws[m][i];
            __nv_bfloat16 h = __float2bfloat16(x);
            g_wbf[m][0][i] = h;
            g_wbf[m][1][i] = __float2bfloat16(x - __bfloat162float(h));
        }
    }
    if (i < HID * INDIM) {
        const float* ws[3] = {wfi, wgi, wti};
        #pragma unroll
        for (int m = 0; m < 3; m++) {
            float x = ws[m][i];
            __nv_bfloat16 h = __float2bfloat16(x);
            g_wbf_in[m][0][i] = h;
            g_wbf_in[m][1][i] = __float2bfloat16(x - __bfloat162float(h));
        }
    }
}

// =========================================================================
// proj kernel via mma.sync (unchanged): 512 threads, grid (2048, 4)
// =========================================================================
#define NTHREADS 512
#define PITCHB 144
#define A_BYTES (256 * PITCHB)
#define B_BYTES (384 * PITCHB)
#define BUF_BYTES (A_BYTES + B_BYTES)
#define PROJ_SMEM (2 * BUF_BYTES)

#define COMPUTE_CHUNK(bb)                                                        \
    do {                                                                         \
        const uint32_t Abase = sbase + (bb) * BUF_BYTES;                         \
        const uint32_t Bbase = Abase + A_BYTES;                                  \
        _Pragma("unroll")                                                        \
        for (int q = 0; q < 4; q++) {                                            \
            const uint32_t koff = q * 32 + tig * 4;                              \
            uint32_t ahi[2][4], alo[2][4];                                       \
            _Pragma("unroll")                                                    \
            for (int f = 0; f < 2; f++) {                                        \
                uint32_t rh = Abase + (uint32_t)((m0w + f * 16 + group) * PITCHB) + koff; \
                ahi[f][0] = lds32(rh);                                           \
                ahi[f][1] = lds32(rh + 8 * PITCHB);                              \
                ahi[f][2] = lds32(rh + 16);                                      \
                ahi[f][3] = lds32(rh + 8 * PITCHB + 16);                         \
                uint32_t rl = rh + 128 * PITCHB;                                 \
                alo[f][0] = lds32(rl);                                           \
                alo[f][1] = lds32(rl + 8 * PITCHB);                              \
                alo[f][2] = lds32(rl + 16);                                      \
                alo[f][3] = lds32(rl + 8 * PITCHB + 16);                         \
            }                                                                    \
            _Pragma("unroll")                                                    \
            for (int mat = 0; mat < 3; mat++) {                                  \
                uint32_t bh[2][2], bl[2][2];                                     \
                _Pragma("unroll")                                                \
                for (int j = 0; j < 2; j++) {                                    \
                    uint32_t rbh = Bbase +                                       \
                        (uint32_t)(((mat * 2) * 64 + n0w + j * 8 + group) * PITCHB) + koff; \
                    bh[j][0] = lds32(rbh); bh[j][1] = lds32(rbh + 16);           \
                    uint32_t rbl = rbh + 64 * PITCHB;                            \
                    bl[j][0] = lds32(rbl); bl[j][1] = lds32(rbl + 16);           \
                }                                                                \
                _Pragma("unroll")                                                \
                for (int j = 0; j < 2; j++)                                      \
                    { mma_bf16(acc[mat][0][j], ahi[0], bh[j]);                   \
                      mma_bf16(acc[mat][1][j], ahi[1], bh[j]); }                 \
                _Pragma("unroll")                                                \
                for (int j = 0; j < 2; j++)                                      \
                    { mma_bf16(acc[mat][0][j], ahi[0], bl[j]);                   \
                      mma_bf16(acc[mat][1][j], ahi[1], bl[j]); }                 \
                _Pragma("unroll")                                                \
                for (int j = 0; j < 2; j++)                                      \
                    { mma_bf16(acc[mat][0][j], alo[0], bh[j]);                   \
                      mma_bf16(acc[mat][1][j], alo[1], bh[j]); }                 \
            }                                                                    \
        }                                                                        \
    } while (0)

__global__ __launch_bounds__(NTHREADS, 1) void proj_mma_kernel(
    const float* __restrict__ x,
    const float* __restrict__ bfa, const float* __restrict__ bfb,
    const float* __restrict__ bga, const float* __restrict__ bgb,
    const float* __restrict__ bta, const float* __restrict__ btb)
{
    extern __shared__ char sm[];
    const uint32_t sbase = smem_to_u32(sm);

    const int tid   = threadIdx.x;
    const int warp  = tid >> 5;
    const int lane  = tid & 31;
    const int group = lane >> 2;
    const int tig   = lane & 3;
    const int m0    = blockIdx.x * 128;
    const int n0    = blockIdx.y * 64;
    const int m0w   = (warp & 3) * 32;
    const int n0w   = (warp >> 2) * 16;
    const int tq    = m0 >> 12;
    const int bq0   = m0 & 4095;

    float acc[3][2][2][4] = {};

    auto stageA = [&](int chunk, int bb) {
        const uint32_t dstb = sbase + bb * BUF_BYTES;
        #pragma unroll
        for (int j = 0; j < 4; j++) {
            int u   = tid + j * NTHREADS;
            int row = u >> 4;
            int f4  = u & 15;
            float4 v = *(const float4*)&x[((((size_t)(bq0 + row) * 3 + chunk) << 6) + tq) * 64 + f4 * 4];
            uint32_t base = dstb + (uint32_t)(row * PITCHB + f4 * 8);
            sts64(base, pack_hi2(v.x, v.y), pack_hi2(v.z, v.w));
            sts64(base + 128 * PITCHB, pack_lo2(v.x, v.y), pack_lo2(v.z, v.w));
        }
    };
    auto stageB = [&](int chunk, int bb) {
        const int kc0 = chunk * 64;
        const uint32_t dstb = sbase + bb * BUF_BYTES + A_BYTES;
        #pragma unroll
        for (int j = 0; j < 6; j++) {
            int u = tid + j * NTHREADS;
            int rg = u >> 9, row = (u >> 3) & 63, kb = u & 7;
            int mat = rg >> 1, sp = rg & 1;
            const __nv_bfloat16* src =
                &g_wbf_in[mat][sp][(size_t)(n0 + row) * INDIM + kc0 + kb * 8];
            uint32_t dst = dstb + (uint32_t)((rg * 64 + row) * PITCHB + kb * 16);
            CP_ASYNC16(dst, src);
        }
    };

    stageB(0, 0); CP_COMMIT();
    stageA(0, 0);
    #pragma unroll 1
    for (int c = 0; c < 3; c++) {
        if (c < 2) {
            stageB(c + 1, (c + 1) & 1); CP_COMMIT();
            stageA(c + 1, (c + 1) & 1);
            CP_WAIT(1);
        } else {
            CP_WAIT(0);
        }
        __syncthreads();
        COMPUTE_CHUNK(c & 1);
        __syncthreads();
    }

    const float* inb[3]  = {bfa, bga, bta};
    const float* hbb[3]  = {bfb, bgb, btb};
    #pragma unroll
    for (int f = 0; f < 2; f++) {
        #pragma unroll
        for (int hh = 0; hh < 2; hh++) {
            const int m = m0w + f * 16 + group + hh * 8;
            const size_t obase = (size_t)(m0 + m) * HID;
            #pragma unroll
            for (int j = 0; j < 2; j++) {
                const int jabs = n0 + n0w + j * 8 + tig * 2;
                #pragma unroll
                for (int mat = 0; mat < 3; mat++) {
                    float2 bi = *(const float2*)&inb[mat][jabs];
                    float2 bh2 = *(const float2*)&hbb[mat][jabs];
                    float2 o;
                    o.x = acc[mat][f][j][hh * 2]     + bi.x + bh2.x;
                    o.y = acc[mat][f][j][hh * 2 + 1] + bi.y + bh2.y;
                    *(float2*)&g_proj[mat][obase + jabs] = o;
                }
            }
        }
    }
}

// =========================================================================
// persistent recurrence: all 64 steps, W resident in smem, h in registers.
// 1024 threads (32 warps, 8m x 4n), CTA tile 256 rows x 32 cols, 128 CTAs.
// =========================================================================
#define STHREADS 1024
#define W_SM_BYTES 98304
#define A_SM_BYTES 65536
#define PERS_SMEM (W_SM_BYTES + 2 * A_SM_BYTES + 128)

__global__ __launch_bounds__(STHREADS, 1) void ltc_persistent_kernel()
{
    extern __shared__ char sm[];
    const uint32_t sW = (smem_to_u32(sm) + 127u) & ~127u;
    const uint32_t sA = sW + W_SM_BYTES;

    const int tid   = threadIdx.x;
    const int warp  = tid >> 5;
    const int lane  = tid & 31;
    const int group = lane >> 2;
    const int tig   = lane & 3;
    const int bx    = blockIdx.x;
    const int b0    = (bx & 15) * 256;
    const int n0    = (bx >> 4) * 32;
    const int m0w   = (warp & 7) * 32;     // 8 m-warps x 32 rows
    const int n0w   = (warp >> 3) * 8;     // 4 n-warps x 8 cols

    // ---- load W once: 6 regions x 32 rows x 512B, XOR-swizzled ----
    #pragma unroll
    for (int j = 0; j < 6; j++) {
        int u   = tid + j * STHREADS;       // 0..6143 16B units
        int rg  = u >> 10;
        int rem = u & 1023;
        int row = rem >> 5;
        int kb  = rem & 31;
        int mat = rg >> 1, sp = rg & 1;
        const __nv_bfloat16* src = &g_wbf[mat][sp][(size_t)(n0 + row) * HID + kb * 8];
        uint32_t dst = sW + (uint32_t)(rg * 16384 + row * 512 + ((kb * 16) ^ ((row & 7) << 4)));
        CP_ASYNC16(dst, src);
    }
    CP_COMMIT(); CP_WAIT(0);
    __syncthreads();

    // h state for this thread's epilogue tile in registers.
    // [f][hh][e] -> b = b0+m0w+f*16+group+hh*8, col = n0+n0w+tig*2+e
    float hvreg[2][2][2] = {};

    #pragma unroll 1
    for (int t = 0; t < T; t++) {
        const __nv_bfloat16* __restrict__ hbf_hi = g_hbf[t & 1][0];
        const __nv_bfloat16* __restrict__ hbf_lo = g_hbf[t & 1][1];

        float acc[3][2][4] = {};   // [mat][mfrag][reg]

        auto stageA = [&](int c, int bb) {
            const int kc0 = c * 64;
            const uint32_t dstb = sA + bb * A_SM_BYTES;
            #pragma unroll
            for (int j = 0; j < 4; j++) {
                int u = tid + j * STHREADS;     // 0..4095 16B units
                int s = u >> 11, row = (u >> 3) & 255, kb = u & 7;
                const __nv_bfloat16* src =
                    (s ? hbf_lo : hbf_hi) + (size_t)(b0 + row) * HID + kc0 + kb * 8;
                uint32_t dst = dstb + (uint32_t)((s * 256 + row) * 128 +
                                                 ((kb * 16) ^ ((row & 7) << 4)));
                CP_ASYNC16(dst, src);
            }
        };

        stageA(0, 0);
        CP_COMMIT();
        #pragma unroll 1
        for (int c = 0; c < 4; c++) {
            if (c < 3) {
                stageA(c + 1, (c + 1) & 1);
                CP_COMMIT();
                CP_WAIT(1);
            } else {
                CP_WAIT(0);
            }
            __syncthreads();
            {
                const uint32_t Ab = sA + (c & 1) * A_SM_BYTES;
                #pragma unroll
                for (int q = 0; q < 4; q++) {
                    const uint32_t pA = (uint32_t)((q * 32 + tig * 4) ^ (group << 4));
                    uint32_t ahi[2][4], alo[2][4];
                    #pragma unroll
                    for (int f = 0; f < 2; f++) {
                        uint32_t rh = Ab + (uint32_t)((m0w + f * 16 + group) * 128) + pA;
                        ahi[f][0] = lds32(rh);        ahi[f][1] = lds32(rh + 1024);
                        ahi[f][2] = lds32(rh ^ 16u);  ahi[f][3] = lds32((rh + 1024) ^ 16u);
                        uint32_t rl = rh + 32768;
                        alo[f][0] = lds32(rl);        alo[f][1] = lds32(rl + 1024);
                        alo[f][2] = lds32(rl ^ 16u);  alo[f][3] = lds32((rl + 1024) ^ 16u);
                    }
                    const uint32_t pB = (uint32_t)((c * 128 + q * 32 + tig * 4) ^ (group << 4));
                    #pragma unroll
                    for (int mat = 0; mat < 3; mat++) {
                        uint32_t bh[2], bl[2];
                        uint32_t rbh = sW + (uint32_t)(mat * 32768) +
                                       (uint32_t)((n0w + group) * 512) + pB;
                        bh[0] = lds32(rbh);  bh[1] = lds32(rbh ^ 16u);
                        uint32_t rbl = rbh + 16384;
                        bl[0] = lds32(rbl);  bl[1] = lds32(rbl ^ 16u);
                        mma_bf16(acc[mat][0], ahi[0], bh);
                        mma_bf16(acc[mat][1], ahi[1], bh);
                        mma_bf16(acc[mat][0], ahi[0], bl);
                        mma_bf16(acc[mat][1], ahi[1], bl);
                        mma_bf16(acc[mat][0], alo[0], bh);
                        mma_bf16(acc[mat][1], alo[1], bh);
                    }
                }
            }
            __syncthreads();
        }

        // ---- fused LTC epilogue (h in registers, fast div) ----
        uint32_t* __restrict__ out_hi = (uint32_t*)g_hbf[(t + 1) & 1][0];
        uint32_t* __restrict__ out_lo = (uint32_t*)g_hbf[(t + 1) & 1][1];
        #pragma unroll
        for (int f = 0; f < 2; f++) {
            #pragma unroll
            for (int hh = 0; hh < 2; hh++) {
                const int r = m0w + f * 16 + group + hh * 8;
                const int b = b0 + r;
                const size_t hrow  = (size_t)b * HID;
                const size_t pbase = ((size_t)t * BATCH + b) * HID;
                const int jabs = n0 + n0w + tig * 2;
                float2 pf = *(const float2*)&g_proj[0][pbase + jabs];
                float2 pg = *(const float2*)&g_proj[1][pbase + jabs];
                float2 pt = *(const float2*)&g_proj[2][pbase + jabs];
                float o2[2];
                #pragma unroll
                for (int e = 0; e < 2; e++) {
                    float rf = acc[0][f][hh * 2 + e];
                    float rg = acc[1][f][hh * 2 + e];
                    float rt = acc[2][f][hh * 2 + e];
                    float pfe = e ? pf.y : pf.x;
                    float pge = e ? pg.y : pg.x;
                    float pte = e ? pt.y : pt.x;
                    float hve = hvreg[f][hh][e];
                    float e2 = __expf(2.f * (pfe + rf));
                    float cand = __fdividef(e2 - 1.f, e2 + 1.f);
                    float gate = __fdividef(1.f, 1.f + __expf(-(pge + rg)));
                    float tau  = 0.5f + 1.5f * __fdividef(1.f, 1.f + __expf(-(pte + rt)));
                    float hn = hve + __fdividef(gate * cand - hve, tau);
                    float e2h = __expf(2.f * hn);
                    o2[e] = __fdividef(e2h - 1.f, e2h + 1.f);
                    hvreg[f][hh][e] = o2[e];
                }
                *(uint32_t*)((char*)out_hi + (hrow + jabs) * 2) = pack_hi2(o2[0], o2[1]);
                *(uint32_t*)((char*)out_lo + (hrow + jabs) * 2) = pack_lo2(o2[0], o2[1]);
            }
        }

        // ---- device-wide barrier (skip after last step) ----
        if (t < T - 1) {
            __threadfence();
            __syncthreads();
            if (tid == 0) {
                unsigned need = (unsigned)(t + 1) * (unsigned)NCTA;
                unsigned arrived = atomicAdd(&g_bar_count, 1u) + 1u;
                if (arrived == need) {
                    atomicExch(&g_bar_phase, (unsigned)(t + 1));
                } else {
                    while (ldcg_u32(&g_bar_phase) < (unsigned)(t + 1)) __nanosleep(64);
                }
                __threadfence();
            }
            __syncthreads();
        }
    }
}

// ---------------- head: h reconstructed from bf16 hi/lo ----------------
__global__ void head_kernel(const float* __restrict__ hw,
                            const float* __restrict__ hb,
                            float* __restrict__ out)
{
    int gwarp = (blockIdx.x * blockDim.x + threadIdx.x) >> 5;
    int lane  = threadIdx.x & 31;
    if (gwarp >= BATCH * 10) return;
    int o = gwarp % 10;
    int b = gwarp / 10;
    const __nv_bfloat16* hhi = g_hbf[0][0];   // T=64 even -> final state parity 0
    const __nv_bfloat16* hlo = g_hbf[0][1];
    float s = 0.f;
    #pragma unroll
    for (int k = lane; k < HID; k += 32) {
        float hv = __bfloat162float(hhi[(size_t)b * HID + k]) +
                   __bfloat162float(hlo[(size_t)b * HID + k]);
        s += hv * hw[o * HID + k];
    }
    #pragma unroll
    for (int off = 16; off; off >>= 1)
        s += __shfl_down_sync(0xffffffffu, s, off);
    if (lane == 0) out[b * 10 + o] = s + hb[o];
}

extern "C" void kernel_launch(void* const* d_in, const int* in_sizes, int n_in,
                              void* d_out, int out_size)
{
    const float* x      = (const float*)d_in[0];
    const float* ffw    = (const float*)d_in[1];
    const float* ffb    = (const float*)d_in[2];
    const float* ffrw   = (const float*)d_in[3];
    const float* ffbias = (const float*)d_in[4];
    const float* gw     = (const float*)d_in[5];
    const float* gb     = (const float*)d_in[6];
    const float* grw    = (const float*)d_in[7];
    const float* gbias  = (const float*)d_in[8];
    const float* tw     = (const float*)d_in[9];
    const float* tb     = (const float*)d_in[10];
    const float* trw    = (const float*)d_in[11];
    const float* tbias  = (const float*)d_in[12];
    const float* hw     = (const float*)d_in[13];
    const float* hb     = (const float*)d_in[14];
    float* out = (float*)d_out;

    cudaFuncSetAttribute(proj_mma_kernel,
                         cudaFuncAttributeMaxDynamicSharedMemorySize, PROJ_SMEM);
    cudaFuncSetAttribute(ltc_persistent_kernel,
                         cudaFuncAttributeMaxDynamicSharedMemorySize, PERS_SMEM);

    // h0 = 0 + barrier counters reset (every replay)
    zero_h_kernel<<<(BATCH * HID + 255) / 256, 256>>>();

    // W (recurrent + input) -> bf16 hi/lo scratch
    wprep_kernel<<<(HID * HID + 255) / 256, 256>>>(ffrw, grw, trw, ffw, gw, tw);

    // all input projections on the tensor pipe
    dim3 pgrid((T * BATCH) / 128, HID / 64);
    proj_mma_kernel<<<pgrid, NTHREADS, PROJ_SMEM>>>(x, ffb, ffbias, gb, gbias, tb, tbias);

    // all 64 LTC steps in one persistent kernel (1024 threads, W resident)
    ltc_persistent_kernel<<<NCTA, STHREADS, PERS_SMEM>>>();

    // classifier head
    head_kernel<<<(BATCH * 10 * 32 + 255) / 256, 256>>>(hw, hb, out);
}